// round 13
// baseline (speedup 1.0000x reference)
#include <cuda_runtime.h>
#include <cuda_fp16.h>
#include <cstdint>

#define B_  2
#define S_  2048
#define HM  1024
#define NH  16
#define NKV 4
#define HD  64
#define WIN 512
#define MROWS (B_*S_)          // 4096
#define NQKV 1536

// ---------------- scratch ----------------------------------------------------
__device__ float g_qkv[MROWS * NQKV];
__device__ __half g_hid_h[MROWS * HM];
__device__ __half g_ao_h [MROWS * HM];
__device__ __half g_wc_h[NQKV * HM],  g_wc_l[NQKV * HM];
__device__ __half g_wo_h[HM * HM],    g_wo_l[HM * HM];
__device__ __half g_qh[MROWS * NH * HD];
__device__ __half g_kh[MROWS * NKV * HD], g_kl[MROWS * NKV * HD];
__device__ __half g_vh[MROWS * NKV * HD];

// ---------------- helpers ----------------------------------------------------
__device__ __forceinline__ uint32_t smem_u32(const void* p) {
    return (uint32_t)__cvta_generic_to_shared(p);
}
__device__ __forceinline__ void cpa16(uint32_t s, const void* g) {
    asm volatile("cp.async.ca.shared.global [%0], [%1], 16;" :: "r"(s), "l"(g));
}
__device__ __forceinline__ void ldsm4(uint32_t* r, uint32_t a) {
    asm volatile("ldmatrix.sync.aligned.m8n8.x4.shared.b16 {%0,%1,%2,%3}, [%4];"
                 : "=r"(r[0]), "=r"(r[1]), "=r"(r[2]), "=r"(r[3]) : "r"(a));
}
__device__ __forceinline__ void ldsm4t(uint32_t* r, uint32_t a) {
    asm volatile("ldmatrix.sync.aligned.m8n8.x4.trans.shared.b16 {%0,%1,%2,%3}, [%4];"
                 : "=r"(r[0]), "=r"(r[1]), "=r"(r[2]), "=r"(r[3]) : "r"(a));
}
__device__ __forceinline__ void mma16816(float* c, const uint32_t* a, const uint32_t* b) {
    asm volatile("mma.sync.aligned.m16n8k16.row.col.f32.f16.f16.f32 "
                 "{%0,%1,%2,%3}, {%4,%5,%6,%7}, {%8,%9}, {%0,%1,%2,%3};"
                 : "+f"(c[0]), "+f"(c[1]), "+f"(c[2]), "+f"(c[3])
                 : "r"(a[0]), "r"(a[1]), "r"(a[2]), "r"(a[3]), "r"(b[0]), "r"(b[1]));
}
__device__ __forceinline__ uint32_t packh2(float lo, float hi) {
    uint32_t r;
    asm("cvt.rn.f16x2.f32 %0, %1, %2;" : "=r"(r) : "f"(hi), "f"(lo));
    return r;
}
__device__ __forceinline__ float hfr(float x) {
    return __half2float(__float2half_rn(x));
}
__device__ __forceinline__ uint32_t swz128(uint32_t o) {   // 128B-row swizzle
    return o ^ ((o >> 3) & 0x70);
}
#define QSCALE (0.125f * 1.4426950408889634f)

// ---------------- fused fp32 -> fp16 (hidden: hi; weights: hi/lo) -----------
__global__ void cvt_all(const float* __restrict__ hidden,
                        const float* __restrict__ Wq, const float* __restrict__ Wk,
                        const float* __restrict__ Wv, const float* __restrict__ Wo,
                        __half* __restrict__ hh,
                        __half* __restrict__ wch, __half* __restrict__ wcl,
                        __half* __restrict__ woh, __half* __restrict__ wol)
{
    int i = blockIdx.x * blockDim.x + threadIdx.x;
    if (i < 1048576) {
        float4 v = ((const float4*)hidden)[i];
        ((__half2*)hh)[2*i]   = __floats2half2_rn(v.x, v.y);
        ((__half2*)hh)[2*i+1] = __floats2half2_rn(v.z, v.w);
        return;
    }
    const float* src; __half *dh, *dl; int o;
    if (i < 1310720)      { src = Wq; dh = wch;               dl = wcl;               o = i - 1048576; }
    else if (i < 1376256) { src = Wk; dh = wch + 1024 * 1024; dl = wcl + 1024 * 1024; o = i - 1310720; }
    else if (i < 1441792) { src = Wv; dh = wch + 1280 * 1024; dl = wcl + 1280 * 1024; o = i - 1376256; }
    else if (i < 1703936) { src = Wo; dh = woh;               dl = wol;               o = i - 1441792; }
    else return;
    float4 v = ((const float4*)src)[o];
    __half h0 = __float2half_rn(v.x), h1 = __float2half_rn(v.y);
    __half h2 = __float2half_rn(v.z), h3 = __float2half_rn(v.w);
    __half l0 = __float2half_rn(v.x - __half2float(h0));
    __half l1 = __float2half_rn(v.y - __half2float(h1));
    __half l2 = __float2half_rn(v.z - __half2float(h2));
    __half l3 = __float2half_rn(v.w - __half2float(h3));
    ((__half2*)dh)[2*o]   = __halves2half2(h0, h1);
    ((__half2*)dh)[2*o+1] = __halves2half2(h2, h3);
    ((__half2*)dl)[2*o]   = __halves2half2(l0, l1);
    ((__half2*)dl)[2*o+1] = __halves2half2(l2, l3);
}

// ---------------- HMMA GEMM: C[M,N] = A[M,K] * B[N,K]^T ---------------------
// fp16 2-pass, BK=64 chunks (128B rows, SW128), 2-stage, 2 CTAs/SM.
#define GTILE   16384             // 128 rows x 128B
#define GSTAGE  (3 * GTILE)       // A, Bh, Bl = 48KB
#define GEMM_SMEM (2 * GSTAGE)    // 96KB

__global__ void __launch_bounds__(256, 2) gemm_tc(
    const __half* __restrict__ Ah, const __half* __restrict__ Bh,
    const __half* __restrict__ Bl,
    float* __restrict__ C, int N, int K)
{
    extern __shared__ char sm[];
    const uint32_t sb = smem_u32(sm);
    const int tid  = threadIdx.x;
    const int lane = tid & 31;
    const int wid  = tid >> 5;
    const int wm   = wid & 1;
    const int wn   = wid >> 1;
    const int m0 = blockIdx.y * 128, n0 = blockIdx.x * 128;
    const int NC = K >> 6;            // 64-wide chunks

    const __half* base0 = Ah + (size_t)m0 * K;
    const __half* base1 = Bh + (size_t)n0 * K;
    const __half* base2 = Bl + (size_t)n0 * K;

    auto issue = [&](int c, int st) {
        const int k0 = c << 6;
        const __half* bs[3] = {base0, base1, base2};
#pragma unroll
        for (int i = 0; i < 12; i++) {
            int idx = tid + i * 256;       // 0..3071
            int tb = idx >> 10; int cc = idx & 1023;
            int rr = cc >> 3, sg = cc & 7;
            uint32_t s = sb + st * GSTAGE + tb * GTILE
                       + swz128((uint32_t)(rr * 128 + sg * 16));
            cpa16(s, bs[tb] + (size_t)rr * K + k0 + sg * 8);
        }
        asm volatile("cp.async.commit_group;" ::: "memory");
    };

    float acc[4][4][4];
#pragma unroll
    for (int mt = 0; mt < 4; mt++)
#pragma unroll
        for (int nt = 0; nt < 4; nt++)
#pragma unroll
            for (int r = 0; r < 4; r++) acc[mt][nt][r] = 0.f;

    const int a_row = lane & 15, a_seg = lane >> 4;
    const int b_g = lane >> 3,  b_r = lane & 7;

    issue(0, 0);
    for (int c = 0; c < NC; c++) {
        const int st = c & 1;
        asm volatile("cp.async.wait_group 0;" ::: "memory");
        __syncthreads();
        if (c + 1 < NC) issue(c + 1, st ^ 1);

        const uint32_t a_b  = sb + st * GSTAGE;
        const uint32_t bh_b = a_b + GTILE;
        const uint32_t bl_b = a_b + 2 * GTILE;

#pragma unroll
        for (int ks = 0; ks < 4; ks++) {
            const uint32_t acol = (uint32_t)(ks * 32 + a_seg * 16);
            const uint32_t bcol = (uint32_t)(ks * 32 + (b_g & 1) * 16);
            uint32_t ah[4][4], bh[2][4], bl[2][4];
#pragma unroll
            for (int mt = 0; mt < 4; mt++) {
                uint32_t ro = (uint32_t)(wm * 64 + mt * 16 + a_row) * 128;
                ldsm4(ah[mt], a_b + swz128(ro + acol));
            }
#pragma unroll
            for (int np = 0; np < 2; np++) {
                uint32_t ro = (uint32_t)(wn * 32 + np * 16 + (b_g >> 1) * 8 + b_r) * 128;
                uint32_t so = swz128(ro + bcol);
                ldsm4(bh[np], bh_b + so);
                ldsm4(bl[np], bl_b + so);
            }
#pragma unroll
            for (int mt = 0; mt < 4; mt++)
#pragma unroll
                for (int nt = 0; nt < 4; nt++) {
                    const uint32_t* fbh = &bh[nt >> 1][(nt & 1) * 2];
                    const uint32_t* fbl = &bl[nt >> 1][(nt & 1) * 2];
                    mma16816(acc[mt][nt], ah[mt], fbh);
                    mma16816(acc[mt][nt], ah[mt], fbl);
                }
        }
    }

    const int g  = lane >> 2;
    const int tc = lane & 3;
#pragma unroll
    for (int mt = 0; mt < 4; mt++) {
        float* r0 = C + (size_t)(m0 + wm * 64 + mt * 16 + g) * N + n0 + wn * 32;
        float* r1 = r0 + 8 * (size_t)N;
#pragma unroll
        for (int nt = 0; nt < 4; nt++) {
            *(float2*)(r0 + nt * 8 + tc * 2) = make_float2(acc[mt][nt][0], acc[mt][nt][1]);
            *(float2*)(r1 + nt * 8 + tc * 2) = make_float2(acc[mt][nt][2], acc[mt][nt][3]);
        }
    }
}

// ---------------- fused RoPE + fp16 split (q hi, k hi/lo, v hi) -------------
__global__ void rope_split(const float* __restrict__ qkv,
                           const float* __restrict__ cosb, const float* __restrict__ sinb,
                           __half* __restrict__ qh,
                           __half* __restrict__ kh, __half* __restrict__ kl,
                           __half* __restrict__ vh)
{
    const int QP = MROWS * NH * 32;
    const int KP = MROWS * NKV * 32;
    const int VP = MROWS * NKV * 32;
    int idx = blockIdx.x * blockDim.x + threadIdx.x;
    if (idx < QP) {
        int d    = idx & 31;
        int head = (idx >> 5) & (NH - 1);
        int bs   = idx >> 9;
        int s    = bs & (S_ - 1);
        size_t pi = (size_t)bs * NQKV + head * HD + d;
        size_t po = (size_t)bs * (NH * HD) + head * HD + d;
        float x0 = qkv[pi], x1 = qkv[pi + 32];
        float c0 = cosb[s * HD + d],      s0 = sinb[s * HD + d];
        float c1 = cosb[s * HD + d + 32], s1 = sinb[s * HD + d + 32];
        qh[po]      = __float2half_rn((x0 * c0 - x1 * s0) * QSCALE);
        qh[po + 32] = __float2half_rn((x1 * c1 + x0 * s1) * QSCALE);
    } else if (idx < QP + KP) {
        int r    = idx - QP;
        int d    = r & 31;
        int head = (r >> 5) & (NKV - 1);
        int bs   = r >> 7;
        int s    = bs & (S_ - 1);
        size_t pi = (size_t)bs * NQKV + 1024 + head * HD + d;
        size_t po = (size_t)bs * (NKV * HD) + head * HD + d;
        float x0 = qkv[pi], x1 = qkv[pi + 32];
        float c0 = cosb[s * HD + d],      s0 = sinb[s * HD + d];
        float c1 = cosb[s * HD + d + 32], s1 = sinb[s * HD + d + 32];
        float y0 = x0 * c0 - x1 * s0;
        float y1 = x1 * c1 + x0 * s1;
        kh[po]      = __float2half_rn(y0); kl[po]      = __float2half_rn(y0 - hfr(y0));
        kh[po + 32] = __float2half_rn(y1); kl[po + 32] = __float2half_rn(y1 - hfr(y1));
    } else if (idx < QP + KP + VP) {
        int r  = (idx - QP - KP) * 2;
        int bs = r >> 8, off = r & 255;
        size_t pi = (size_t)bs * NQKV + 1280 + off;
        ((__half2*)vh)[r >> 1] = __floats2half2_rn(qkv[pi], qkv[pi + 1]);
    }
}

// ---------------- fp16 flash attention (V single pass, 4 CTAs/SM) -----------
// S = Qh*(Kh+Kl); O += Ph*Vh. 6 smem buffers of 9216B.
#define ATB 9216
#define ATT_SMEM (6 * ATB)

__global__ void __launch_bounds__(128, 4) attn_tc(
    const __half* __restrict__ Qh,
    const __half* __restrict__ Kh, const __half* __restrict__ Kl,
    const __half* __restrict__ Vh,
    __half* __restrict__ Oh)
{
    extern __shared__ char sm[];
    const uint32_t sb = smem_u32(sm);
    // stage0: b1,b2,b3 ; stage1: b4,b5,b0 (b0 = Q buffer, recycled)
    const uint32_t kbh[2] = {sb + 1 * ATB, sb + 4 * ATB};
    const uint32_t kbl[2] = {sb + 2 * ATB, sb + 5 * ATB};
    const uint32_t vbh[2] = {sb + 3 * ATB, sb + 0 * ATB};

    const int qt = blockIdx.x, h = blockIdx.y, b = blockIdx.z;
    const int q0 = qt * 64;
    const int kv = h >> 2;
    const int tid = threadIdx.x, lane = tid & 31, w = tid >> 5;

    const int t0 = max(0, qt - 8);
    const int t1 = qt;

    auto load_kv = [&](int t, int st) {
        const size_t rb = ((size_t)(b * S_) + t * 64) * (NKV * HD) + kv * HD;
        const __half* src[3] = {Kh + rb, Kl + rb, Vh + rb};
        const uint32_t dst[3] = {kbh[st], kbl[st], vbh[st]};
#pragma unroll
        for (int i = 0; i < 12; i++) {
            int c = tid + i * 128;         // 0..1535
            int tb = c >> 9; int cc = c & 511;
            int rr = cc >> 3, sg = cc & 7;
            cpa16(dst[tb] + rr * 144 + sg * 16,
                  src[tb] + (size_t)rr * (NKV * HD) + sg * 8);
        }
        asm volatile("cp.async.commit_group;" ::: "memory");
    };

    {
        const __half* gqh = Qh + ((size_t)(b * S_) + q0) * (NH * HD) + h * HD;
#pragma unroll
        for (int i = 0; i < 4; i++) {
            int c = tid + i * 128;
            int rr = c >> 3, sg = c & 7;
            cpa16(sb + rr * 144 + sg * 16, gqh + (size_t)rr * (NH * HD) + sg * 8);
        }
    }
    load_kv(t0, 0);
    asm volatile("cp.async.wait_group 0;" ::: "memory");
    __syncthreads();

    uint32_t qf[4][4];
    {
        const uint32_t ro = (uint32_t)(w * 16 + (lane & 15)) * 144 + (lane >> 4) * 16;
#pragma unroll
        for (int ks = 0; ks < 4; ks++)
            ldsm4(qf[ks], sb + ro + ks * 32);
    }
    __syncthreads();                       // b0 free for stage-1 V
    if (t0 < t1) load_kv(t0 + 1, 1);

    const int r0 = q0 + w * 16 + (lane >> 2);
    const int r1 = r0 + 8;
    float m0 = -1e30f, m1 = -1e30f, l0 = 0.f, l1 = 0.f;
    float oacc[8][4];
#pragma unroll
    for (int nt = 0; nt < 8; nt++)
#pragma unroll
        for (int c = 0; c < 4; c++) oacc[nt][c] = 0.f;

    for (int t = t0; t <= t1; t++) {
        const int st = (t - t0) & 1;
        const bool domask = (t == t1) || (t == t0 && qt >= 8);

        float sacc[8][4];
#pragma unroll
        for (int nt = 0; nt < 8; nt++)
#pragma unroll
            for (int c = 0; c < 4; c++) sacc[nt][c] = 0.f;

        const uint32_t kro = (uint32_t)(lane & 15) * 144 + (lane >> 4) * 16;
#pragma unroll
        for (int ks = 0; ks < 4; ks++) {
#pragma unroll
            for (int ntp = 0; ntp < 4; ntp++) {
                uint32_t kh[4], kl[4];
                uint32_t ro = kro + (uint32_t)(ntp * 16) * 144 + ks * 32;
                ldsm4(kh, kbh[st] + ro);
                ldsm4(kl, kbl[st] + ro);
                uint32_t bh0[2] = {kh[0], kh[2]}, bh1[2] = {kh[1], kh[3]};
                uint32_t bl0[2] = {kl[0], kl[2]}, bl1[2] = {kl[1], kl[3]};
                mma16816(sacc[2*ntp],   qf[ks], bh0);
                mma16816(sacc[2*ntp+1], qf[ks], bh1);
                mma16816(sacc[2*ntp],   qf[ks], bl0);
                mma16816(sacc[2*ntp+1], qf[ks], bl1);
            }
        }

        float mx0 = -3e30f, mx1 = -3e30f;
        if (domask) {
#pragma unroll
            for (int nt = 0; nt < 8; nt++) {
                int kj = t * 64 + nt * 8 + 2 * (lane & 3);
                float v0 = ((kj   <= r0) && (r0 - kj   < WIN)) ? sacc[nt][0] : -3e30f;
                float v1 = ((kj+1 <= r0) && (r0 - kj-1 < WIN)) ? sacc[nt][1] : -3e30f;
                float v2 = ((kj   <= r1) && (r1 - kj   < WIN)) ? sacc[nt][2] : -3e30f;
                float v3 = ((kj+1 <= r1) && (r1 - kj-1 < WIN)) ? sacc[nt][3] : -3e30f;
                sacc[nt][0] = v0; sacc[nt][1] = v1; sacc[nt][2] = v2; sacc[nt][3] = v3;
                mx0 = fmaxf(mx0, fmaxf(v0, v1));
                mx1 = fmaxf(mx1, fmaxf(v2, v3));
            }
        } else {
#pragma unroll
            for (int nt = 0; nt < 8; nt++) {
                mx0 = fmaxf(mx0, fmaxf(sacc[nt][0], sacc[nt][1]));
                mx1 = fmaxf(mx1, fmaxf(sacc[nt][2], sacc[nt][3]));
            }
        }
        mx0 = fmaxf(mx0, __shfl_xor_sync(0xffffffffu, mx0, 1));
        mx0 = fmaxf(mx0, __shfl_xor_sync(0xffffffffu, mx0, 2));
        mx1 = fmaxf(mx1, __shfl_xor_sync(0xffffffffu, mx1, 1));
        mx1 = fmaxf(mx1, __shfl_xor_sync(0xffffffffu, mx1, 2));

        float mn0 = fmaxf(m0, mx0), mn1 = fmaxf(m1, mx1);
        float al0 = exp2f(m0 - mn0), al1 = exp2f(m1 - mn1);
        m0 = mn0; m1 = mn1;

        float rs0 = 0.f, rs1 = 0.f;
#pragma unroll
        for (int nt = 0; nt < 8; nt++) {
            float p0 = exp2f(sacc[nt][0] - mn0);
            float p1 = exp2f(sacc[nt][1] - mn0);
            float p2 = exp2f(sacc[nt][2] - mn1);
            float p3 = exp2f(sacc[nt][3] - mn1);
            sacc[nt][0] = p0; sacc[nt][1] = p1; sacc[nt][2] = p2; sacc[nt][3] = p3;
            rs0 += p0 + p1; rs1 += p2 + p3;
        }
        rs0 += __shfl_xor_sync(0xffffffffu, rs0, 1);
        rs0 += __shfl_xor_sync(0xffffffffu, rs0, 2);
        rs1 += __shfl_xor_sync(0xffffffffu, rs1, 1);
        rs1 += __shfl_xor_sync(0xffffffffu, rs1, 2);
        l0 = l0 * al0 + rs0; l1 = l1 * al1 + rs1;
#pragma unroll
        for (int nt = 0; nt < 8; nt++) {
            oacc[nt][0] *= al0; oacc[nt][1] *= al0;
            oacc[nt][2] *= al1; oacc[nt][3] *= al1;
        }

#pragma unroll
        for (int pk = 0; pk < 4; pk++) {
            uint32_t ah[4];
            ah[0] = packh2(sacc[2*pk][0],   sacc[2*pk][1]);
            ah[1] = packh2(sacc[2*pk][2],   sacc[2*pk][3]);
            ah[2] = packh2(sacc[2*pk+1][0], sacc[2*pk+1][1]);
            ah[3] = packh2(sacc[2*pk+1][2], sacc[2*pk+1][3]);
            const uint32_t vro = (uint32_t)(pk * 16 + (lane & 15)) * 144
                               + (uint32_t)(lane >> 4) * 16;
#pragma unroll
            for (int dp = 0; dp < 4; dp++) {
                uint32_t vh[4];
                ldsm4t(vh, vbh[st] + vro + dp * 32);
                mma16816(oacc[2*dp],   ah, &vh[0]);
                mma16816(oacc[2*dp+1], ah, &vh[2]);
            }
        }

        if (t < t1) {
            __syncthreads();
            if (t + 2 <= t1) {
                load_kv(t + 2, st);
                asm volatile("cp.async.wait_group 1;" ::: "memory");
            } else {
                asm volatile("cp.async.wait_group 0;" ::: "memory");
            }
            __syncthreads();
        }
    }

    const float inv0 = 1.f / l0, inv1 = 1.f / l1;
    const size_t rowA = (size_t)(b * S_) + r0;
    const size_t rowB = rowA + 8;
    const int colb = h * HD + 2 * (lane & 3);
#pragma unroll
    for (int nt = 0; nt < 8; nt++) {
        size_t offA = rowA * (NH * HD) + colb + nt * 8;
        size_t offB = rowB * (NH * HD) + colb + nt * 8;
        *(uint32_t*)(Oh + offA) = packh2(oacc[nt][0] * inv0, oacc[nt][1] * inv0);
        *(uint32_t*)(Oh + offB) = packh2(oacc[nt][2] * inv1, oacc[nt][3] * inv1);
    }
}

// ---------------- launch -----------------------------------------------------
extern "C" void kernel_launch(void* const* d_in, const int* in_sizes, int n_in,
                              void* d_out, int out_size)
{
    const float* hidden = (const float*)d_in[0];
    const float* cosb   = (const float*)d_in[1];
    const float* sinb   = (const float*)d_in[2];
    const float* Wq = (const float*)d_in[4];
    const float* Wk = (const float*)d_in[5];
    const float* Wv = (const float*)d_in[6];
    const float* Wo = (const float*)d_in[7];
    float* out = (float*)d_out;

    float* qkv;
    cudaGetSymbolAddress((void**)&qkv, g_qkv);
    __half *hh, *aoh, *wch, *wcl, *woh, *wol;
    __half *qh, *kh, *kl, *vh;
    cudaGetSymbolAddress((void**)&hh,  g_hid_h);
    cudaGetSymbolAddress((void**)&aoh, g_ao_h);
    cudaGetSymbolAddress((void**)&wch, g_wc_h);  cudaGetSymbolAddress((void**)&wcl, g_wc_l);
    cudaGetSymbolAddress((void**)&woh, g_wo_h);  cudaGetSymbolAddress((void**)&wol, g_wo_l);
    cudaGetSymbolAddress((void**)&qh,  g_qh);
    cudaGetSymbolAddress((void**)&kh,  g_kh);    cudaGetSymbolAddress((void**)&kl,  g_kl);
    cudaGetSymbolAddress((void**)&vh,  g_vh);

    cudaFuncSetAttribute(gemm_tc, cudaFuncAttributeMaxDynamicSharedMemorySize, GEMM_SMEM);
    cudaFuncSetAttribute(attn_tc, cudaFuncAttributeMaxDynamicSharedMemorySize, ATT_SMEM);

    cvt_all<<<(1703936 + 255) / 256, 256>>>(hidden, Wq, Wk, Wv, Wo,
                                            hh, wch, wcl, woh, wol);

    gemm_tc<<<dim3(NQKV / 128, MROWS / 128), 256, GEMM_SMEM>>>(hh, wch, wcl, qkv, NQKV, HM);

    int total = MROWS * NH * 32 + MROWS * NKV * 32 + MROWS * NKV * 32;
    rope_split<<<(total + 255) / 256, 256>>>(qkv, cosb, sinb, qh, kh, kl, vh);

    attn_tc<<<dim3(S_ / 64, NH, B_), 128, ATT_SMEM>>>(qh, kh, kl, vh, aoh);

    gemm_tc<<<dim3(HM / 128, MROWS / 128), 256, GEMM_SMEM>>>(aoh, woh, wol, out, HM, HM);
}

// round 14
// speedup vs baseline: 1.1239x; 1.1239x over previous
#include <cuda_runtime.h>
#include <cuda_fp16.h>
#include <cstdint>

#define B_  2
#define S_  2048
#define HM  1024
#define NH  16
#define NKV 4
#define HD  64
#define WIN 512
#define MROWS (B_*S_)          // 4096
#define NQKV 1536

// ---------------- scratch ----------------------------------------------------
__device__ float g_qkv[MROWS * NQKV];
__device__ __half g_hid_h[MROWS * HM];
__device__ __half g_ao_h [MROWS * HM];
__device__ __half g_wc_h[NQKV * HM],  g_wc_l[NQKV * HM];
__device__ __half g_wo_h[HM * HM],    g_wo_l[HM * HM];
__device__ __half g_qh[MROWS * NH * HD];
__device__ __half g_kh[MROWS * NKV * HD], g_kl[MROWS * NKV * HD];
__device__ __half g_vh[MROWS * NKV * HD];

// ---------------- helpers ----------------------------------------------------
__device__ __forceinline__ uint32_t smem_u32(const void* p) {
    return (uint32_t)__cvta_generic_to_shared(p);
}
__device__ __forceinline__ void cpa16(uint32_t s, const void* g) {
    asm volatile("cp.async.ca.shared.global [%0], [%1], 16;" :: "r"(s), "l"(g));
}
__device__ __forceinline__ void ldsm4(uint32_t* r, uint32_t a) {
    asm volatile("ldmatrix.sync.aligned.m8n8.x4.shared.b16 {%0,%1,%2,%3}, [%4];"
                 : "=r"(r[0]), "=r"(r[1]), "=r"(r[2]), "=r"(r[3]) : "r"(a));
}
__device__ __forceinline__ void ldsm4t(uint32_t* r, uint32_t a) {
    asm volatile("ldmatrix.sync.aligned.m8n8.x4.trans.shared.b16 {%0,%1,%2,%3}, [%4];"
                 : "=r"(r[0]), "=r"(r[1]), "=r"(r[2]), "=r"(r[3]) : "r"(a));
}
__device__ __forceinline__ void mma16816(float* c, const uint32_t* a, const uint32_t* b) {
    asm volatile("mma.sync.aligned.m16n8k16.row.col.f32.f16.f16.f32 "
                 "{%0,%1,%2,%3}, {%4,%5,%6,%7}, {%8,%9}, {%0,%1,%2,%3};"
                 : "+f"(c[0]), "+f"(c[1]), "+f"(c[2]), "+f"(c[3])
                 : "r"(a[0]), "r"(a[1]), "r"(a[2]), "r"(a[3]), "r"(b[0]), "r"(b[1]));
}
__device__ __forceinline__ uint32_t packh2(float lo, float hi) {
    uint32_t r;
    asm("cvt.rn.f16x2.f32 %0, %1, %2;" : "=r"(r) : "f"(hi), "f"(lo));
    return r;
}
__device__ __forceinline__ float hfr(float x) {
    return __half2float(__float2half_rn(x));
}
__device__ __forceinline__ uint32_t swz64(uint32_t o) {
    return o ^ ((o >> 3) & 0x30);
}
#define QSCALE (0.125f * 1.4426950408889634f)

// ---------------- fused fp32 -> fp16 (hidden: hi; weights: hi/lo) -----------
__global__ void cvt_all(const float* __restrict__ hidden,
                        const float* __restrict__ Wq, const float* __restrict__ Wk,
                        const float* __restrict__ Wv, const float* __restrict__ Wo,
                        __half* __restrict__ hh,
                        __half* __restrict__ wch, __half* __restrict__ wcl,
                        __half* __restrict__ woh, __half* __restrict__ wol)
{
    int i = blockIdx.x * blockDim.x + threadIdx.x;
    if (i < 1048576) {
        float4 v = ((const float4*)hidden)[i];
        ((__half2*)hh)[2*i]   = __floats2half2_rn(v.x, v.y);
        ((__half2*)hh)[2*i+1] = __floats2half2_rn(v.z, v.w);
        return;
    }
    const float* src; __half *dh, *dl; int o;
    if (i < 1310720)      { src = Wq; dh = wch;               dl = wcl;               o = i - 1048576; }
    else if (i < 1376256) { src = Wk; dh = wch + 1024 * 1024; dl = wcl + 1024 * 1024; o = i - 1310720; }
    else if (i < 1441792) { src = Wv; dh = wch + 1280 * 1024; dl = wcl + 1280 * 1024; o = i - 1376256; }
    else if (i < 1703936) { src = Wo; dh = woh;               dl = wol;               o = i - 1441792; }
    else return;
    float4 v = ((const float4*)src)[o];
    __half h0 = __float2half_rn(v.x), h1 = __float2half_rn(v.y);
    __half h2 = __float2half_rn(v.z), h3 = __float2half_rn(v.w);
    __half l0 = __float2half_rn(v.x - __half2float(h0));
    __half l1 = __float2half_rn(v.y - __half2float(h1));
    __half l2 = __float2half_rn(v.z - __half2float(h2));
    __half l3 = __float2half_rn(v.w - __half2float(h3));
    ((__half2*)dh)[2*o]   = __halves2half2(h0, h1);
    ((__half2*)dh)[2*o+1] = __halves2half2(h2, h3);
    ((__half2*)dl)[2*o]   = __halves2half2(l0, l1);
    ((__half2*)dl)[2*o+1] = __halves2half2(l2, l3);
}

// ---------------- HMMA GEMM (R12 config): BK=32, SW64, 3-stage, 2 CTA/SM ----
#define TILE_B   8192
#define STAGE_B  (3 * TILE_B)     // 24KB
#define GEMM_SMEM (3 * STAGE_B)   // 72KB

__global__ void __launch_bounds__(256, 2) gemm_tc(
    const __half* __restrict__ Ah, const __half* __restrict__ Bh,
    const __half* __restrict__ Bl,
    float* __restrict__ C, int N, int K)
{
    extern __shared__ char sm[];
    const uint32_t sb = smem_u32(sm);
    const int tid  = threadIdx.x;
    const int lane = tid & 31;
    const int wid  = tid >> 5;
    const int wm   = wid & 1;
    const int wn   = wid >> 1;
    const int m0 = blockIdx.y * 128, n0 = blockIdx.x * 128;
    const int NC = K >> 5;

    const __half* base0 = Ah + (size_t)m0 * K;
    const __half* base1 = Bh + (size_t)n0 * K;
    const __half* base2 = Bl + (size_t)n0 * K;

    int cp_t[6], cp_row[6], cp_seg[6];
#pragma unroll
    for (int i = 0; i < 6; i++) {
        int idx = tid + i * 256;
        cp_t[i] = idx >> 9; int cc = idx & 511;
        cp_row[i] = cc >> 2; cp_seg[i] = cc & 3;
    }

    auto issue = [&](int c, int st) {
        const int k0 = c << 5;
        const __half* bs[3] = {base0, base1, base2};
#pragma unroll
        for (int i = 0; i < 6; i++) {
            uint32_t s = sb + st * STAGE_B + cp_t[i] * TILE_B
                       + swz64((uint32_t)(cp_row[i] * 64 + cp_seg[i] * 16));
            cpa16(s, bs[cp_t[i]] + (size_t)cp_row[i] * K + k0 + cp_seg[i] * 8);
        }
        asm volatile("cp.async.commit_group;" ::: "memory");
    };

    float acc[4][4][4];
#pragma unroll
    for (int mt = 0; mt < 4; mt++)
#pragma unroll
        for (int nt = 0; nt < 4; nt++)
#pragma unroll
            for (int r = 0; r < 4; r++) acc[mt][nt][r] = 0.f;

    const int a_row = lane & 15, a_seg = lane >> 4;
    const int b_g = lane >> 3,  b_r = lane & 7;

    issue(0, 0);
    issue(1, 1);
    for (int c = 0; c < NC; c++) {
        const int st = c % 3;
        if (c == NC - 1) {
            asm volatile("cp.async.wait_group 0;" ::: "memory");
        } else {
            asm volatile("cp.async.wait_group 1;" ::: "memory");
        }
        __syncthreads();

        const uint32_t a_b  = sb + st * STAGE_B;
        const uint32_t bh_b = a_b + TILE_B;
        const uint32_t bl_b = a_b + 2 * TILE_B;

#pragma unroll
        for (int ks = 0; ks < 2; ks++) {
            const uint32_t acol = (uint32_t)(ks * 32 + a_seg * 16);
            const uint32_t bcol = (uint32_t)(ks * 32 + (b_g & 1) * 16);
            uint32_t ah[4][4], bh[2][4], bl[2][4];
#pragma unroll
            for (int mt = 0; mt < 4; mt++) {
                uint32_t ro = (uint32_t)(wm * 64 + mt * 16 + a_row) * 64;
                ldsm4(ah[mt], a_b + swz64(ro + acol));
            }
#pragma unroll
            for (int np = 0; np < 2; np++) {
                uint32_t ro = (uint32_t)(wn * 32 + np * 16 + (b_g >> 1) * 8 + b_r) * 64;
                uint32_t so = swz64(ro + bcol);
                ldsm4(bh[np], bh_b + so);
                ldsm4(bl[np], bl_b + so);
            }
#pragma unroll
            for (int mt = 0; mt < 4; mt++)
#pragma unroll
                for (int nt = 0; nt < 4; nt++) {
                    const uint32_t* fbh = &bh[nt >> 1][(nt & 1) * 2];
                    const uint32_t* fbl = &bl[nt >> 1][(nt & 1) * 2];
                    mma16816(acc[mt][nt], ah[mt], fbh);
                    mma16816(acc[mt][nt], ah[mt], fbl);
                }
        }
        if (c + 2 < NC) issue(c + 2, (c + 2) % 3);
    }

    const int g  = lane >> 2;
    const int tc = lane & 3;
#pragma unroll
    for (int mt = 0; mt < 4; mt++) {
        float* r0 = C + (size_t)(m0 + wm * 64 + mt * 16 + g) * N + n0 + wn * 32;
        float* r1 = r0 + 8 * (size_t)N;
#pragma unroll
        for (int nt = 0; nt < 4; nt++) {
            *(float2*)(r0 + nt * 8 + tc * 2) = make_float2(acc[mt][nt][0], acc[mt][nt][1]);
            *(float2*)(r1 + nt * 8 + tc * 2) = make_float2(acc[mt][nt][2], acc[mt][nt][3]);
        }
    }
}

// ---------------- fused RoPE + fp16 split (q hi, k hi/lo, v hi) -------------
__global__ void rope_split(const float* __restrict__ qkv,
                           const float* __restrict__ cosb, const float* __restrict__ sinb,
                           __half* __restrict__ qh,
                           __half* __restrict__ kh, __half* __restrict__ kl,
                           __half* __restrict__ vh)
{
    const int QP = MROWS * NH * 32;
    const int KP = MROWS * NKV * 32;
    const int VP = MROWS * NKV * 32;
    int idx = blockIdx.x * blockDim.x + threadIdx.x;
    if (idx < QP) {
        int d    = idx & 31;
        int head = (idx >> 5) & (NH - 1);
        int bs   = idx >> 9;
        int s    = bs & (S_ - 1);
        size_t pi = (size_t)bs * NQKV + head * HD + d;
        size_t po = (size_t)bs * (NH * HD) + head * HD + d;
        float x0 = qkv[pi], x1 = qkv[pi + 32];
        float c0 = cosb[s * HD + d],      s0 = sinb[s * HD + d];
        float c1 = cosb[s * HD + d + 32], s1 = sinb[s * HD + d + 32];
        qh[po]      = __float2half_rn((x0 * c0 - x1 * s0) * QSCALE);
        qh[po + 32] = __float2half_rn((x1 * c1 + x0 * s1) * QSCALE);
    } else if (idx < QP + KP) {
        int r    = idx - QP;
        int d    = r & 31;
        int head = (r >> 5) & (NKV - 1);
        int bs   = r >> 7;
        int s    = bs & (S_ - 1);
        size_t pi = (size_t)bs * NQKV + 1024 + head * HD + d;
        size_t po = (size_t)bs * (NKV * HD) + head * HD + d;
        float x0 = qkv[pi], x1 = qkv[pi + 32];
        float c0 = cosb[s * HD + d],      s0 = sinb[s * HD + d];
        float c1 = cosb[s * HD + d + 32], s1 = sinb[s * HD + d + 32];
        float y0 = x0 * c0 - x1 * s0;
        float y1 = x1 * c1 + x0 * s1;
        kh[po]      = __float2half_rn(y0); kl[po]      = __float2half_rn(y0 - hfr(y0));
        kh[po + 32] = __float2half_rn(y1); kl[po + 32] = __float2half_rn(y1 - hfr(y1));
    } else if (idx < QP + KP + VP) {
        int r  = (idx - QP - KP) * 2;
        int bs = r >> 8, off = r & 255;
        size_t pi = (size_t)bs * NQKV + 1280 + off;
        ((__half2*)vh)[r >> 1] = __floats2half2_rn(qkv[pi], qkv[pi + 1]);
    }
}

// ---------------- fp16 flash attention (V single pass, 4 CTAs/SM) -----------
#define ATB 9216
#define ATT_SMEM (6 * ATB)

__global__ void __launch_bounds__(128, 4) attn_tc(
    const __half* __restrict__ Qh,
    const __half* __restrict__ Kh, const __half* __restrict__ Kl,
    const __half* __restrict__ Vh,
    __half* __restrict__ Oh)
{
    extern __shared__ char sm[];
    const uint32_t sb = smem_u32(sm);
    const uint32_t kbh[2] = {sb + 1 * ATB, sb + 4 * ATB};
    const uint32_t kbl[2] = {sb + 2 * ATB, sb + 5 * ATB};
    const uint32_t vbh[2] = {sb + 3 * ATB, sb + 0 * ATB};

    const int qt = blockIdx.x, h = blockIdx.y, b = blockIdx.z;
    const int q0 = qt * 64;
    const int kv = h >> 2;
    const int tid = threadIdx.x, lane = tid & 31, w = tid >> 5;

    const int t0 = max(0, qt - 8);
    const int t1 = qt;

    auto load_kv = [&](int t, int st) {
        const size_t rb = ((size_t)(b * S_) + t * 64) * (NKV * HD) + kv * HD;
        const __half* src[3] = {Kh + rb, Kl + rb, Vh + rb};
        const uint32_t dst[3] = {kbh[st], kbl[st], vbh[st]};
#pragma unroll
        for (int i = 0; i < 12; i++) {
            int c = tid + i * 128;
            int tb = c >> 9; int cc = c & 511;
            int rr = cc >> 3, sg = cc & 7;
            cpa16(dst[tb] + rr * 144 + sg * 16,
                  src[tb] + (size_t)rr * (NKV * HD) + sg * 8);
        }
        asm volatile("cp.async.commit_group;" ::: "memory");
    };

    {
        const __half* gqh = Qh + ((size_t)(b * S_) + q0) * (NH * HD) + h * HD;
#pragma unroll
        for (int i = 0; i < 4; i++) {
            int c = tid + i * 128;
            int rr = c >> 3, sg = c & 7;
            cpa16(sb + rr * 144 + sg * 16, gqh + (size_t)rr * (NH * HD) + sg * 8);
        }
    }
    load_kv(t0, 0);
    asm volatile("cp.async.wait_group 0;" ::: "memory");
    __syncthreads();

    uint32_t qf[4][4];
    {
        const uint32_t ro = (uint32_t)(w * 16 + (lane & 15)) * 144 + (lane >> 4) * 16;
#pragma unroll
        for (int ks = 0; ks < 4; ks++)
            ldsm4(qf[ks], sb + ro + ks * 32);
    }
    __syncthreads();
    if (t0 < t1) load_kv(t0 + 1, 1);

    const int r0 = q0 + w * 16 + (lane >> 2);
    const int r1 = r0 + 8;
    float m0 = -1e30f, m1 = -1e30f, l0 = 0.f, l1 = 0.f;
    float oacc[8][4];
#pragma unroll
    for (int nt = 0; nt < 8; nt++)
#pragma unroll
        for (int c = 0; c < 4; c++) oacc[nt][c] = 0.f;

    for (int t = t0; t <= t1; t++) {
        const int st = (t - t0) & 1;
        const bool domask = (t == t1) || (t == t0 && qt >= 8);

        float sacc[8][4];
#pragma unroll
        for (int nt = 0; nt < 8; nt++)
#pragma unroll
            for (int c = 0; c < 4; c++) sacc[nt][c] = 0.f;

        const uint32_t kro = (uint32_t)(lane & 15) * 144 + (lane >> 4) * 16;
#pragma unroll
        for (int ks = 0; ks < 4; ks++) {
#pragma unroll
            for (int ntp = 0; ntp < 4; ntp++) {
                uint32_t kh[4], kl[4];
                uint32_t ro = kro + (uint32_t)(ntp * 16) * 144 + ks * 32;
                ldsm4(kh, kbh[st] + ro);
                ldsm4(kl, kbl[st] + ro);
                uint32_t bh0[2] = {kh[0], kh[2]}, bh1[2] = {kh[1], kh[3]};
                uint32_t bl0[2] = {kl[0], kl[2]}, bl1[2] = {kl[1], kl[3]};
                mma16816(sacc[2*ntp],   qf[ks], bh0);
                mma16816(sacc[2*ntp+1], qf[ks], bh1);
                mma16816(sacc[2*ntp],   qf[ks], bl0);
                mma16816(sacc[2*ntp+1], qf[ks], bl1);
            }
        }

        float mx0 = -3e30f, mx1 = -3e30f;
        if (domask) {
#pragma unroll
            for (int nt = 0; nt < 8; nt++) {
                int kj = t * 64 + nt * 8 + 2 * (lane & 3);
                float v0 = ((kj   <= r0) && (r0 - kj   < WIN)) ? sacc[nt][0] : -3e30f;
                float v1 = ((kj+1 <= r0) && (r0 - kj-1 < WIN)) ? sacc[nt][1] : -3e30f;
                float v2 = ((kj   <= r1) && (r1 - kj   < WIN)) ? sacc[nt][2] : -3e30f;
                float v3 = ((kj+1 <= r1) && (r1 - kj-1 < WIN)) ? sacc[nt][3] : -3e30f;
                sacc[nt][0] = v0; sacc[nt][1] = v1; sacc[nt][2] = v2; sacc[nt][3] = v3;
                mx0 = fmaxf(mx0, fmaxf(v0, v1));
                mx1 = fmaxf(mx1, fmaxf(v2, v3));
            }
        } else {
#pragma unroll
            for (int nt = 0; nt < 8; nt++) {
                mx0 = fmaxf(mx0, fmaxf(sacc[nt][0], sacc[nt][1]));
                mx1 = fmaxf(mx1, fmaxf(sacc[nt][2], sacc[nt][3]));
            }
        }
        mx0 = fmaxf(mx0, __shfl_xor_sync(0xffffffffu, mx0, 1));
        mx0 = fmaxf(mx0, __shfl_xor_sync(0xffffffffu, mx0, 2));
        mx1 = fmaxf(mx1, __shfl_xor_sync(0xffffffffu, mx1, 1));
        mx1 = fmaxf(mx1, __shfl_xor_sync(0xffffffffu, mx1, 2));

        float mn0 = fmaxf(m0, mx0), mn1 = fmaxf(m1, mx1);
        float al0 = exp2f(m0 - mn0), al1 = exp2f(m1 - mn1);
        m0 = mn0; m1 = mn1;

        float rs0 = 0.f, rs1 = 0.f;
#pragma unroll
        for (int nt = 0; nt < 8; nt++) {
            float p0 = exp2f(sacc[nt][0] - mn0);
            float p1 = exp2f(sacc[nt][1] - mn0);
            float p2 = exp2f(sacc[nt][2] - mn1);
            float p3 = exp2f(sacc[nt][3] - mn1);
            sacc[nt][0] = p0; sacc[nt][1] = p1; sacc[nt][2] = p2; sacc[nt][3] = p3;
            rs0 += p0 + p1; rs1 += p2 + p3;
        }
        rs0 += __shfl_xor_sync(0xffffffffu, rs0, 1);
        rs0 += __shfl_xor_sync(0xffffffffu, rs0, 2);
        rs1 += __shfl_xor_sync(0xffffffffu, rs1, 1);
        rs1 += __shfl_xor_sync(0xffffffffu, rs1, 2);
        l0 = l0 * al0 + rs0; l1 = l1 * al1 + rs1;
#pragma unroll
        for (int nt = 0; nt < 8; nt++) {
            oacc[nt][0] *= al0; oacc[nt][1] *= al0;
            oacc[nt][2] *= al1; oacc[nt][3] *= al1;
        }

#pragma unroll
        for (int pk = 0; pk < 4; pk++) {
            uint32_t ah[4];
            ah[0] = packh2(sacc[2*pk][0],   sacc[2*pk][1]);
            ah[1] = packh2(sacc[2*pk][2],   sacc[2*pk][3]);
            ah[2] = packh2(sacc[2*pk+1][0], sacc[2*pk+1][1]);
            ah[3] = packh2(sacc[2*pk+1][2], sacc[2*pk+1][3]);
            const uint32_t vro = (uint32_t)(pk * 16 + (lane & 15)) * 144
                               + (uint32_t)(lane >> 4) * 16;
#pragma unroll
            for (int dp = 0; dp < 4; dp++) {
                uint32_t vh[4];
                ldsm4t(vh, vbh[st] + vro + dp * 32);
                mma16816(oacc[2*dp],   ah, &vh[0]);
                mma16816(oacc[2*dp+1], ah, &vh[2]);
            }
        }

        if (t < t1) {
            __syncthreads();
            if (t + 2 <= t1) {
                load_kv(t + 2, st);
                asm volatile("cp.async.wait_group 1;" ::: "memory");
            } else {
                asm volatile("cp.async.wait_group 0;" ::: "memory");
            }
            __syncthreads();
        }
    }

    const float inv0 = 1.f / l0, inv1 = 1.f / l1;
    const size_t rowA = (size_t)(b * S_) + r0;
    const size_t rowB = rowA + 8;
    const int colb = h * HD + 2 * (lane & 3);
#pragma unroll
    for (int nt = 0; nt < 8; nt++) {
        size_t offA = rowA * (NH * HD) + colb + nt * 8;
        size_t offB = rowB * (NH * HD) + colb + nt * 8;
        *(uint32_t*)(Oh + offA) = packh2(oacc[nt][0] * inv0, oacc[nt][1] * inv0);
        *(uint32_t*)(Oh + offB) = packh2(oacc[nt][2] * inv1, oacc[nt][3] * inv1);
    }
}

// ---------------- launch -----------------------------------------------------
extern "C" void kernel_launch(void* const* d_in, const int* in_sizes, int n_in,
                              void* d_out, int out_size)
{
    const float* hidden = (const float*)d_in[0];
    const float* cosb   = (const float*)d_in[1];
    const float* sinb   = (const float*)d_in[2];
    const float* Wq = (const float*)d_in[4];
    const float* Wk = (const float*)d_in[5];
    const float* Wv = (const float*)d_in[6];
    const float* Wo = (const float*)d_in[7];
    float* out = (float*)d_out;

    float* qkv;
    cudaGetSymbolAddress((void**)&qkv, g_qkv);
    __half *hh, *aoh, *wch, *wcl, *woh, *wol;
    __half *qh, *kh, *kl, *vh;
    cudaGetSymbolAddress((void**)&hh,  g_hid_h);
    cudaGetSymbolAddress((void**)&aoh, g_ao_h);
    cudaGetSymbolAddress((void**)&wch, g_wc_h);  cudaGetSymbolAddress((void**)&wcl, g_wc_l);
    cudaGetSymbolAddress((void**)&woh, g_wo_h);  cudaGetSymbolAddress((void**)&wol, g_wo_l);
    cudaGetSymbolAddress((void**)&qh,  g_qh);
    cudaGetSymbolAddress((void**)&kh,  g_kh);    cudaGetSymbolAddress((void**)&kl,  g_kl);
    cudaGetSymbolAddress((void**)&vh,  g_vh);

    cudaFuncSetAttribute(gemm_tc, cudaFuncAttributeMaxDynamicSharedMemorySize, GEMM_SMEM);
    cudaFuncSetAttribute(attn_tc, cudaFuncAttributeMaxDynamicSharedMemorySize, ATT_SMEM);

    cvt_all<<<(1703936 + 255) / 256, 256>>>(hidden, Wq, Wk, Wv, Wo,
                                            hh, wch, wcl, woh, wol);

    gemm_tc<<<dim3(NQKV / 128, MROWS / 128), 256, GEMM_SMEM>>>(hh, wch, wcl, qkv, NQKV, HM);

    int total = MROWS * NH * 32 + MROWS * NKV * 32 + MROWS * NKV * 32;
    rope_split<<<(total + 255) / 256, 256>>>(qkv, cosb, sinb, qh, kh, kl, vh);

    attn_tc<<<dim3(S_ / 64, NH, B_), 128, ATT_SMEM>>>(qh, kh, kl, vh, aoh);

    gemm_tc<<<dim3(HM / 128, MROWS / 128), 256, GEMM_SMEM>>>(aoh, woh, wol, out, HM, HM);
}

// round 15
// speedup vs baseline: 1.1837x; 1.0532x over previous
#include <cuda_runtime.h>
#include <cuda_fp16.h>
#include <cstdint>

#define B_  2
#define S_  2048
#define HM  1024
#define NH  16
#define NKV 4
#define HD  64
#define WIN 512
#define MROWS (B_*S_)          // 4096
#define NQKV 1536

// ---------------- scratch ----------------------------------------------------
__device__ float g_qkv[MROWS * NQKV];
__device__ __half g_hid_h[MROWS * HM];
__device__ __half g_ao_h [MROWS * HM];
__device__ __half g_wc_h[NQKV * HM],  g_wc_l[NQKV * HM];
__device__ __half g_wo_h[HM * HM];
__device__ __half g_qh[MROWS * NH * HD];
__device__ __half g_kh[MROWS * NKV * HD], g_kl[MROWS * NKV * HD];
__device__ __half g_vh[MROWS * NKV * HD];

// ---------------- helpers ----------------------------------------------------
__device__ __forceinline__ uint32_t smem_u32(const void* p) {
    return (uint32_t)__cvta_generic_to_shared(p);
}
__device__ __forceinline__ void cpa16(uint32_t s, const void* g) {
    asm volatile("cp.async.ca.shared.global [%0], [%1], 16;" :: "r"(s), "l"(g));
}
__device__ __forceinline__ void ldsm4(uint32_t* r, uint32_t a) {
    asm volatile("ldmatrix.sync.aligned.m8n8.x4.shared.b16 {%0,%1,%2,%3}, [%4];"
                 : "=r"(r[0]), "=r"(r[1]), "=r"(r[2]), "=r"(r[3]) : "r"(a));
}
__device__ __forceinline__ void ldsm4t(uint32_t* r, uint32_t a) {
    asm volatile("ldmatrix.sync.aligned.m8n8.x4.trans.shared.b16 {%0,%1,%2,%3}, [%4];"
                 : "=r"(r[0]), "=r"(r[1]), "=r"(r[2]), "=r"(r[3]) : "r"(a));
}
__device__ __forceinline__ void mma16816(float* c, const uint32_t* a, const uint32_t* b) {
    asm volatile("mma.sync.aligned.m16n8k16.row.col.f32.f16.f16.f32 "
                 "{%0,%1,%2,%3}, {%4,%5,%6,%7}, {%8,%9}, {%0,%1,%2,%3};"
                 : "+f"(c[0]), "+f"(c[1]), "+f"(c[2]), "+f"(c[3])
                 : "r"(a[0]), "r"(a[1]), "r"(a[2]), "r"(a[3]), "r"(b[0]), "r"(b[1]));
}
__device__ __forceinline__ uint32_t packh2(float lo, float hi) {
    uint32_t r;
    asm("cvt.rn.f16x2.f32 %0, %1, %2;" : "=r"(r) : "f"(hi), "f"(lo));
    return r;
}
__device__ __forceinline__ float hfr(float x) {
    return __half2float(__float2half_rn(x));
}
__device__ __forceinline__ uint32_t swz64(uint32_t o) {
    return o ^ ((o >> 3) & 0x30);
}
#define QSCALE (0.125f * 1.4426950408889634f)

// ---------------- fused fp32 -> fp16 (lo only for Wk) ------------------------
__global__ void cvt_all(const float* __restrict__ hidden,
                        const float* __restrict__ Wq, const float* __restrict__ Wk,
                        const float* __restrict__ Wv, const float* __restrict__ Wo,
                        __half* __restrict__ hh,
                        __half* __restrict__ wch, __half* __restrict__ wcl,
                        __half* __restrict__ woh)
{
    int i = blockIdx.x * blockDim.x + threadIdx.x;
    const float* src; __half* dh; int o; bool dolo = false; __half* dl = nullptr;
    if (i < 1048576)      { src = hidden; dh = hh;  o = i; }
    else if (i < 1310720) { src = Wq; dh = wch;               o = i - 1048576; }
    else if (i < 1376256) { src = Wk; dh = wch + 1024 * 1024; o = i - 1310720;
                            dolo = true; dl = wcl + 1024 * 1024; }
    else if (i < 1441792) { src = Wv; dh = wch + 1280 * 1024; o = i - 1376256; }
    else if (i < 1703936) { src = Wo; dh = woh;               o = i - 1441792; }
    else return;
    float4 v = ((const float4*)src)[o];
    __half h0 = __float2half_rn(v.x), h1 = __float2half_rn(v.y);
    __half h2 = __float2half_rn(v.z), h3 = __float2half_rn(v.w);
    ((__half2*)dh)[2*o]   = __halves2half2(h0, h1);
    ((__half2*)dh)[2*o+1] = __halves2half2(h2, h3);
    if (dolo) {
        __half l0 = __float2half_rn(v.x - __half2float(h0));
        __half l1 = __float2half_rn(v.y - __half2float(h1));
        __half l2 = __float2half_rn(v.z - __half2float(h2));
        __half l3 = __float2half_rn(v.w - __half2float(h3));
        ((__half2*)dl)[2*o]   = __halves2half2(l0, l1);
        ((__half2*)dl)[2*o+1] = __halves2half2(l2, l3);
    }
}

// ---------------- HMMA GEMM: BK=32, SW64, 3-stage, 2 CTA/SM -----------------
// lo-pass (B residual) only for output columns in [loBeg, loEnd).
#define TILE_B   8192
#define STAGE_B  (3 * TILE_B)     // 24KB
#define GEMM_SMEM (3 * STAGE_B)   // 72KB

__global__ void __launch_bounds__(256, 2) gemm_tc(
    const __half* __restrict__ Ah, const __half* __restrict__ Bh,
    const __half* __restrict__ Bl,
    float* __restrict__ C, int N, int K, int loBeg, int loEnd)
{
    extern __shared__ char sm[];
    const uint32_t sb = smem_u32(sm);
    const int tid  = threadIdx.x;
    const int lane = tid & 31;
    const int wid  = tid >> 5;
    const int wm   = wid & 1;
    const int wn   = wid >> 1;
    const int m0 = blockIdx.y * 128, n0 = blockIdx.x * 128;
    const int NC = K >> 5;
    const bool use_lo = (n0 >= loBeg) && (n0 < loEnd);

    const __half* base0 = Ah + (size_t)m0 * K;
    const __half* base1 = Bh + (size_t)n0 * K;
    const __half* base2 = Bl + (size_t)n0 * K;

    int cp_t[6], cp_row[6], cp_seg[6];
#pragma unroll
    for (int i = 0; i < 6; i++) {
        int idx = tid + i * 256;
        cp_t[i] = idx >> 9; int cc = idx & 511;
        cp_row[i] = cc >> 2; cp_seg[i] = cc & 3;
    }

    auto issue = [&](int c, int st) {
        const int k0 = c << 5;
        const __half* bs[3] = {base0, base1, base2};
#pragma unroll
        for (int i = 0; i < 6; i++) {
            if (cp_t[i] == 2 && !use_lo) continue;
            uint32_t s = sb + st * STAGE_B + cp_t[i] * TILE_B
                       + swz64((uint32_t)(cp_row[i] * 64 + cp_seg[i] * 16));
            cpa16(s, bs[cp_t[i]] + (size_t)cp_row[i] * K + k0 + cp_seg[i] * 8);
        }
        asm volatile("cp.async.commit_group;" ::: "memory");
    };

    float acc[4][4][4];
#pragma unroll
    for (int mt = 0; mt < 4; mt++)
#pragma unroll
        for (int nt = 0; nt < 4; nt++)
#pragma unroll
            for (int r = 0; r < 4; r++) acc[mt][nt][r] = 0.f;

    const int a_row = lane & 15, a_seg = lane >> 4;
    const int b_g = lane >> 3,  b_r = lane & 7;

    issue(0, 0);
    issue(1, 1);
    for (int c = 0; c < NC; c++) {
        const int st = c % 3;
        if (c == NC - 1) {
            asm volatile("cp.async.wait_group 0;" ::: "memory");
        } else {
            asm volatile("cp.async.wait_group 1;" ::: "memory");
        }
        __syncthreads();

        const uint32_t a_b  = sb + st * STAGE_B;
        const uint32_t bh_b = a_b + TILE_B;
        const uint32_t bl_b = a_b + 2 * TILE_B;

#pragma unroll
        for (int ks = 0; ks < 2; ks++) {
            const uint32_t acol = (uint32_t)(ks * 32 + a_seg * 16);
            const uint32_t bcol = (uint32_t)(ks * 32 + (b_g & 1) * 16);
            uint32_t ah[4][4], bh[2][4], bl[2][4];
#pragma unroll
            for (int mt = 0; mt < 4; mt++) {
                uint32_t ro = (uint32_t)(wm * 64 + mt * 16 + a_row) * 64;
                ldsm4(ah[mt], a_b + swz64(ro + acol));
            }
#pragma unroll
            for (int np = 0; np < 2; np++) {
                uint32_t ro = (uint32_t)(wn * 32 + np * 16 + (b_g >> 1) * 8 + b_r) * 64;
                uint32_t so = swz64(ro + bcol);
                ldsm4(bh[np], bh_b + so);
                if (use_lo) ldsm4(bl[np], bl_b + so);
            }
#pragma unroll
            for (int mt = 0; mt < 4; mt++)
#pragma unroll
                for (int nt = 0; nt < 4; nt++) {
                    const uint32_t* fbh = &bh[nt >> 1][(nt & 1) * 2];
                    mma16816(acc[mt][nt], ah[mt], fbh);
                    if (use_lo) {
                        const uint32_t* fbl = &bl[nt >> 1][(nt & 1) * 2];
                        mma16816(acc[mt][nt], ah[mt], fbl);
                    }
                }
        }
        if (c + 2 < NC) issue(c + 2, (c + 2) % 3);
    }

    const int g  = lane >> 2;
    const int tc = lane & 3;
#pragma unroll
    for (int mt = 0; mt < 4; mt++) {
        float* r0 = C + (size_t)(m0 + wm * 64 + mt * 16 + g) * N + n0 + wn * 32;
        float* r1 = r0 + 8 * (size_t)N;
#pragma unroll
        for (int nt = 0; nt < 4; nt++) {
            *(float2*)(r0 + nt * 8 + tc * 2) = make_float2(acc[mt][nt][0], acc[mt][nt][1]);
            *(float2*)(r1 + nt * 8 + tc * 2) = make_float2(acc[mt][nt][2], acc[mt][nt][3]);
        }
    }
}

// ---------------- fused RoPE + fp16 split (q hi, k hi/lo, v hi) -------------
__global__ void rope_split(const float* __restrict__ qkv,
                           const float* __restrict__ cosb, const float* __restrict__ sinb,
                           __half* __restrict__ qh,
                           __half* __restrict__ kh, __half* __restrict__ kl,
                           __half* __restrict__ vh)
{
    const int QP = MROWS * NH * 32;
    const int KP = MROWS * NKV * 32;
    const int VP = MROWS * NKV * 32;
    int idx = blockIdx.x * blockDim.x + threadIdx.x;
    if (idx < QP) {
        int d    = idx & 31;
        int head = (idx >> 5) & (NH - 1);
        int bs   = idx >> 9;
        int s    = bs & (S_ - 1);
        size_t pi = (size_t)bs * NQKV + head * HD + d;
        size_t po = (size_t)bs * (NH * HD) + head * HD + d;
        float x0 = qkv[pi], x1 = qkv[pi + 32];
        float c0 = cosb[s * HD + d],      s0 = sinb[s * HD + d];
        float c1 = cosb[s * HD + d + 32], s1 = sinb[s * HD + d + 32];
        qh[po]      = __float2half_rn((x0 * c0 - x1 * s0) * QSCALE);
        qh[po + 32] = __float2half_rn((x1 * c1 + x0 * s1) * QSCALE);
    } else if (idx < QP + KP) {
        int r    = idx - QP;
        int d    = r & 31;
        int head = (r >> 5) & (NKV - 1);
        int bs   = r >> 7;
        int s    = bs & (S_ - 1);
        size_t pi = (size_t)bs * NQKV + 1024 + head * HD + d;
        size_t po = (size_t)bs * (NKV * HD) + head * HD + d;
        float x0 = qkv[pi], x1 = qkv[pi + 32];
        float c0 = cosb[s * HD + d],      s0 = sinb[s * HD + d];
        float c1 = cosb[s * HD + d + 32], s1 = sinb[s * HD + d + 32];
        float y0 = x0 * c0 - x1 * s0;
        float y1 = x1 * c1 + x0 * s1;
        kh[po]      = __float2half_rn(y0); kl[po]      = __float2half_rn(y0 - hfr(y0));
        kh[po + 32] = __float2half_rn(y1); kl[po + 32] = __float2half_rn(y1 - hfr(y1));
    } else if (idx < QP + KP + VP) {
        int r  = (idx - QP - KP) * 2;
        int bs = r >> 8, off = r & 255;
        size_t pi = (size_t)bs * NQKV + 1280 + off;
        ((__half2*)vh)[r >> 1] = __floats2half2_rn(qkv[pi], qkv[pi + 1]);
    }
}

// ---------------- fp16 flash attention (V single pass, 4 CTAs/SM) -----------
#define ATB 9216
#define ATT_SMEM (6 * ATB)

__global__ void __launch_bounds__(128, 4) attn_tc(
    const __half* __restrict__ Qh,
    const __half* __restrict__ Kh, const __half* __restrict__ Kl,
    const __half* __restrict__ Vh,
    __half* __restrict__ Oh)
{
    extern __shared__ char sm[];
    const uint32_t sb = smem_u32(sm);
    const uint32_t kbh[2] = {sb + 1 * ATB, sb + 4 * ATB};
    const uint32_t kbl[2] = {sb + 2 * ATB, sb + 5 * ATB};
    const uint32_t vbh[2] = {sb + 3 * ATB, sb + 0 * ATB};

    const int qt = blockIdx.x, h = blockIdx.y, b = blockIdx.z;
    const int q0 = qt * 64;
    const int kv = h >> 2;
    const int tid = threadIdx.x, lane = tid & 31, w = tid >> 5;

    const int t0 = max(0, qt - 8);
    const int t1 = qt;

    auto load_kv = [&](int t, int st) {
        const size_t rb = ((size_t)(b * S_) + t * 64) * (NKV * HD) + kv * HD;
        const __half* src[3] = {Kh + rb, Kl + rb, Vh + rb};
        const uint32_t dst[3] = {kbh[st], kbl[st], vbh[st]};
#pragma unroll
        for (int i = 0; i < 12; i++) {
            int c = tid + i * 128;
            int tb = c >> 9; int cc = c & 511;
            int rr = cc >> 3, sg = cc & 7;
            cpa16(dst[tb] + rr * 144 + sg * 16,
                  src[tb] + (size_t)rr * (NKV * HD) + sg * 8);
        }
        asm volatile("cp.async.commit_group;" ::: "memory");
    };

    {
        const __half* gqh = Qh + ((size_t)(b * S_) + q0) * (NH * HD) + h * HD;
#pragma unroll
        for (int i = 0; i < 4; i++) {
            int c = tid + i * 128;
            int rr = c >> 3, sg = c & 7;
            cpa16(sb + rr * 144 + sg * 16, gqh + (size_t)rr * (NH * HD) + sg * 8);
        }
    }
    load_kv(t0, 0);
    asm volatile("cp.async.wait_group 0;" ::: "memory");
    __syncthreads();

    uint32_t qf[4][4];
    {
        const uint32_t ro = (uint32_t)(w * 16 + (lane & 15)) * 144 + (lane >> 4) * 16;
#pragma unroll
        for (int ks = 0; ks < 4; ks++)
            ldsm4(qf[ks], sb + ro + ks * 32);
    }
    __syncthreads();
    if (t0 < t1) load_kv(t0 + 1, 1);

    const int r0 = q0 + w * 16 + (lane >> 2);
    const int r1 = r0 + 8;
    float m0 = -1e30f, m1 = -1e30f, l0 = 0.f, l1 = 0.f;
    float oacc[8][4];
#pragma unroll
    for (int nt = 0; nt < 8; nt++)
#pragma unroll
        for (int c = 0; c < 4; c++) oacc[nt][c] = 0.f;

    for (int t = t0; t <= t1; t++) {
        const int st = (t - t0) & 1;
        const bool domask = (t == t1) || (t == t0 && qt >= 8);

        float sacc[8][4];
#pragma unroll
        for (int nt = 0; nt < 8; nt++)
#pragma unroll
            for (int c = 0; c < 4; c++) sacc[nt][c] = 0.f;

        const uint32_t kro = (uint32_t)(lane & 15) * 144 + (lane >> 4) * 16;
#pragma unroll
        for (int ks = 0; ks < 4; ks++) {
#pragma unroll
            for (int ntp = 0; ntp < 4; ntp++) {
                uint32_t kh[4], kl[4];
                uint32_t ro = kro + (uint32_t)(ntp * 16) * 144 + ks * 32;
                ldsm4(kh, kbh[st] + ro);
                ldsm4(kl, kbl[st] + ro);
                uint32_t bh0[2] = {kh[0], kh[2]}, bh1[2] = {kh[1], kh[3]};
                uint32_t bl0[2] = {kl[0], kl[2]}, bl1[2] = {kl[1], kl[3]};
                mma16816(sacc[2*ntp],   qf[ks], bh0);
                mma16816(sacc[2*ntp+1], qf[ks], bh1);
                mma16816(sacc[2*ntp],   qf[ks], bl0);
                mma16816(sacc[2*ntp+1], qf[ks], bl1);
            }
        }

        float mx0 = -3e30f, mx1 = -3e30f;
        if (domask) {
#pragma unroll
            for (int nt = 0; nt < 8; nt++) {
                int kj = t * 64 + nt * 8 + 2 * (lane & 3);
                float v0 = ((kj   <= r0) && (r0 - kj   < WIN)) ? sacc[nt][0] : -3e30f;
                float v1 = ((kj+1 <= r0) && (r0 - kj-1 < WIN)) ? sacc[nt][1] : -3e30f;
                float v2 = ((kj   <= r1) && (r1 - kj   < WIN)) ? sacc[nt][2] : -3e30f;
                float v3 = ((kj+1 <= r1) && (r1 - kj-1 < WIN)) ? sacc[nt][3] : -3e30f;
                sacc[nt][0] = v0; sacc[nt][1] = v1; sacc[nt][2] = v2; sacc[nt][3] = v3;
                mx0 = fmaxf(mx0, fmaxf(v0, v1));
                mx1 = fmaxf(mx1, fmaxf(v2, v3));
            }
        } else {
#pragma unroll
            for (int nt = 0; nt < 8; nt++) {
                mx0 = fmaxf(mx0, fmaxf(sacc[nt][0], sacc[nt][1]));
                mx1 = fmaxf(mx1, fmaxf(sacc[nt][2], sacc[nt][3]));
            }
        }
        mx0 = fmaxf(mx0, __shfl_xor_sync(0xffffffffu, mx0, 1));
        mx0 = fmaxf(mx0, __shfl_xor_sync(0xffffffffu, mx0, 2));
        mx1 = fmaxf(mx1, __shfl_xor_sync(0xffffffffu, mx1, 1));
        mx1 = fmaxf(mx1, __shfl_xor_sync(0xffffffffu, mx1, 2));

        float mn0 = fmaxf(m0, mx0), mn1 = fmaxf(m1, mx1);
        float al0 = exp2f(m0 - mn0), al1 = exp2f(m1 - mn1);
        m0 = mn0; m1 = mn1;

        float rs0 = 0.f, rs1 = 0.f;
#pragma unroll
        for (int nt = 0; nt < 8; nt++) {
            float p0 = exp2f(sacc[nt][0] - mn0);
            float p1 = exp2f(sacc[nt][1] - mn0);
            float p2 = exp2f(sacc[nt][2] - mn1);
            float p3 = exp2f(sacc[nt][3] - mn1);
            sacc[nt][0] = p0; sacc[nt][1] = p1; sacc[nt][2] = p2; sacc[nt][3] = p3;
            rs0 += p0 + p1; rs1 += p2 + p3;
        }
        rs0 += __shfl_xor_sync(0xffffffffu, rs0, 1);
        rs0 += __shfl_xor_sync(0xffffffffu, rs0, 2);
        rs1 += __shfl_xor_sync(0xffffffffu, rs1, 1);
        rs1 += __shfl_xor_sync(0xffffffffu, rs1, 2);
        l0 = l0 * al0 + rs0; l1 = l1 * al1 + rs1;
#pragma unroll
        for (int nt = 0; nt < 8; nt++) {
            oacc[nt][0] *= al0; oacc[nt][1] *= al0;
            oacc[nt][2] *= al1; oacc[nt][3] *= al1;
        }

#pragma unroll
        for (int pk = 0; pk < 4; pk++) {
            uint32_t ah[4];
            ah[0] = packh2(sacc[2*pk][0],   sacc[2*pk][1]);
            ah[1] = packh2(sacc[2*pk][2],   sacc[2*pk][3]);
            ah[2] = packh2(sacc[2*pk+1][0], sacc[2*pk+1][1]);
            ah[3] = packh2(sacc[2*pk+1][2], sacc[2*pk+1][3]);
            const uint32_t vro = (uint32_t)(pk * 16 + (lane & 15)) * 144
                               + (uint32_t)(lane >> 4) * 16;
#pragma unroll
            for (int dp = 0; dp < 4; dp++) {
                uint32_t vh[4];
                ldsm4t(vh, vbh[st] + vro + dp * 32);
                mma16816(oacc[2*dp],   ah, &vh[0]);
                mma16816(oacc[2*dp+1], ah, &vh[2]);
            }
        }

        if (t < t1) {
            __syncthreads();
            if (t + 2 <= t1) {
                load_kv(t + 2, st);
                asm volatile("cp.async.wait_group 1;" ::: "memory");
            } else {
                asm volatile("cp.async.wait_group 0;" ::: "memory");
            }
            __syncthreads();
        }
    }

    const float inv0 = 1.f / l0, inv1 = 1.f / l1;
    const size_t rowA = (size_t)(b * S_) + r0;
    const size_t rowB = rowA + 8;
    const int colb = h * HD + 2 * (lane & 3);
#pragma unroll
    for (int nt = 0; nt < 8; nt++) {
        size_t offA = rowA * (NH * HD) + colb + nt * 8;
        size_t offB = rowB * (NH * HD) + colb + nt * 8;
        *(uint32_t*)(Oh + offA) = packh2(oacc[nt][0] * inv0, oacc[nt][1] * inv0);
        *(uint32_t*)(Oh + offB) = packh2(oacc[nt][2] * inv1, oacc[nt][3] * inv1);
    }
}

// ---------------- launch -----------------------------------------------------
extern "C" void kernel_launch(void* const* d_in, const int* in_sizes, int n_in,
                              void* d_out, int out_size)
{
    const float* hidden = (const float*)d_in[0];
    const float* cosb   = (const float*)d_in[1];
    const float* sinb   = (const float*)d_in[2];
    const float* Wq = (const float*)d_in[4];
    const float* Wk = (const float*)d_in[5];
    const float* Wv = (const float*)d_in[6];
    const float* Wo = (const float*)d_in[7];
    float* out = (float*)d_out;

    float* qkv;
    cudaGetSymbolAddress((void**)&qkv, g_qkv);
    __half *hh, *aoh, *wch, *wcl, *woh;
    __half *qh, *kh, *kl, *vh;
    cudaGetSymbolAddress((void**)&hh,  g_hid_h);
    cudaGetSymbolAddress((void**)&aoh, g_ao_h);
    cudaGetSymbolAddress((void**)&wch, g_wc_h);  cudaGetSymbolAddress((void**)&wcl, g_wc_l);
    cudaGetSymbolAddress((void**)&woh, g_wo_h);
    cudaGetSymbolAddress((void**)&qh,  g_qh);
    cudaGetSymbolAddress((void**)&kh,  g_kh);    cudaGetSymbolAddress((void**)&kl,  g_kl);
    cudaGetSymbolAddress((void**)&vh,  g_vh);

    cudaFuncSetAttribute(gemm_tc, cudaFuncAttributeMaxDynamicSharedMemorySize, GEMM_SMEM);
    cudaFuncSetAttribute(attn_tc, cudaFuncAttributeMaxDynamicSharedMemorySize, ATT_SMEM);

    cvt_all<<<(1703936 + 255) / 256, 256>>>(hidden, Wq, Wk, Wv, Wo,
                                            hh, wch, wcl, woh);

    // QKV projection: lo-pass only for K columns [1024, 1280)
    gemm_tc<<<dim3(NQKV / 128, MROWS / 128), 256, GEMM_SMEM>>>(
        hh, wch, wcl, qkv, NQKV, HM, 1024, 1280);

    int total = MROWS * NH * 32 + MROWS * NKV * 32 + MROWS * NKV * 32;
    rope_split<<<(total + 255) / 256, 256>>>(qkv, cosb, sinb, qh, kh, kl, vh);

    attn_tc<<<dim3(S_ / 64, NH, B_), 128, ATT_SMEM>>>(qh, kh, kl, vh, aoh);

    // Wo projection: pure single-pass fp16
    gemm_tc<<<dim3(HM / 128, MROWS / 128), 256, GEMM_SMEM>>>(
        aoh, woh, woh, out, HM, HM, 0, 0);
}

// round 17
// speedup vs baseline: 1.6214x; 1.3698x over previous
#include <cuda_runtime.h>
#include <cuda_fp16.h>
#include <cstdint>

#define B_  2
#define S_  2048
#define HM  1024
#define NH  16
#define NKV 4
#define HD  64
#define WIN 512
#define MROWS (B_*S_)          // 4096
#define NQKV 1536

// ---------------- scratch ----------------------------------------------------
__device__ float g_qkv[MROWS * NQKV];
__device__ __half g_hid_h[MROWS * HM];
__device__ __half g_ao_h [MROWS * HM];
__device__ __half g_wc_h[NQKV * HM];
__device__ __half g_wo_h[HM * HM];
__device__ __half g_qh[MROWS * NH * HD];
__device__ __half g_kh[MROWS * NKV * HD];
__device__ __half g_vh[MROWS * NKV * HD];

// ---------------- helpers ----------------------------------------------------
__device__ __forceinline__ uint32_t smem_u32(const void* p) {
    return (uint32_t)__cvta_generic_to_shared(p);
}
__device__ __forceinline__ void cpa16(uint32_t s, const void* g) {
    asm volatile("cp.async.ca.shared.global [%0], [%1], 16;" :: "r"(s), "l"(g));
}
__device__ __forceinline__ void ldsm4(uint32_t* r, uint32_t a) {
    asm volatile("ldmatrix.sync.aligned.m8n8.x4.shared.b16 {%0,%1,%2,%3}, [%4];"
                 : "=r"(r[0]), "=r"(r[1]), "=r"(r[2]), "=r"(r[3]) : "r"(a));
}
__device__ __forceinline__ void ldsm4t(uint32_t* r, uint32_t a) {
    asm volatile("ldmatrix.sync.aligned.m8n8.x4.trans.shared.b16 {%0,%1,%2,%3}, [%4];"
                 : "=r"(r[0]), "=r"(r[1]), "=r"(r[2]), "=r"(r[3]) : "r"(a));
}
__device__ __forceinline__ void mma16816(float* c, const uint32_t* a, const uint32_t* b) {
    asm volatile("mma.sync.aligned.m16n8k16.row.col.f32.f16.f16.f32 "
                 "{%0,%1,%2,%3}, {%4,%5,%6,%7}, {%8,%9}, {%0,%1,%2,%3};"
                 : "+f"(c[0]), "+f"(c[1]), "+f"(c[2]), "+f"(c[3])
                 : "r"(a[0]), "r"(a[1]), "r"(a[2]), "r"(a[3]), "r"(b[0]), "r"(b[1]));
}
__device__ __forceinline__ uint32_t packh2(float lo, float hi) {
    uint32_t r;
    asm("cvt.rn.f16x2.f32 %0, %1, %2;" : "=r"(r) : "f"(hi), "f"(lo));
    return r;
}
__device__ __forceinline__ uint32_t swz64(uint32_t o) {
    return o ^ ((o >> 3) & 0x30);
}
#define QSCALE (0.125f * 1.4426950408889634f)

// ---------------- fused fp32 -> fp16 (all single precision-level) -----------
__global__ void cvt_all(const float* __restrict__ hidden,
                        const float* __restrict__ Wq, const float* __restrict__ Wk,
                        const float* __restrict__ Wv, const float* __restrict__ Wo,
                        __half* __restrict__ hh,
                        __half* __restrict__ wch, __half* __restrict__ woh)
{
    int i = blockIdx.x * blockDim.x + threadIdx.x;
    const float* src; __half* dh; int o;
    if (i < 1048576)      { src = hidden; dh = hh;  o = i; }
    else if (i < 1310720) { src = Wq; dh = wch;               o = i - 1048576; }
    else if (i < 1376256) { src = Wk; dh = wch + 1024 * 1024; o = i - 1310720; }
    else if (i < 1441792) { src = Wv; dh = wch + 1280 * 1024; o = i - 1376256; }
    else if (i < 1703936) { src = Wo; dh = woh;               o = i - 1441792; }
    else return;
    float4 v = ((const float4*)src)[o];
    ((__half2*)dh)[2*o]   = __floats2half2_rn(v.x, v.y);
    ((__half2*)dh)[2*o+1] = __floats2half2_rn(v.z, v.w);
}

// ---------------- HMMA GEMM: single-pass fp16, BK=32, SW64, 3-stage ---------
#define TILE_B   8192
#define STAGE_B  (2 * TILE_B)     // A, B = 16KB
#define GEMM_SMEM (3 * STAGE_B)   // 48KB

__global__ void __launch_bounds__(256, 2) gemm_tc(
    const __half* __restrict__ Ah, const __half* __restrict__ Bh,
    float* __restrict__ C, int N, int K)
{
    extern __shared__ char sm[];
    const uint32_t sb = smem_u32(sm);
    const int tid  = threadIdx.x;
    const int lane = tid & 31;
    const int wid  = tid >> 5;
    const int wm   = wid & 1;
    const int wn   = wid >> 1;
    const int m0 = blockIdx.y * 128, n0 = blockIdx.x * 128;
    const int NC = K >> 5;

    const __half* base0 = Ah + (size_t)m0 * K;
    const __half* base1 = Bh + (size_t)n0 * K;

    int cp_t[4], cp_row[4], cp_seg[4];
#pragma unroll
    for (int i = 0; i < 4; i++) {
        int idx = tid + i * 256;
        cp_t[i] = idx >> 9; int cc = idx & 511;
        cp_row[i] = cc >> 2; cp_seg[i] = cc & 3;
    }

    auto issue = [&](int c, int st) {
        const int k0 = c << 5;
        const __half* bs[2] = {base0, base1};
#pragma unroll
        for (int i = 0; i < 4; i++) {
            uint32_t s = sb + st * STAGE_B + cp_t[i] * TILE_B
                       + swz64((uint32_t)(cp_row[i] * 64 + cp_seg[i] * 16));
            cpa16(s, bs[cp_t[i]] + (size_t)cp_row[i] * K + k0 + cp_seg[i] * 8);
        }
        asm volatile("cp.async.commit_group;" ::: "memory");
    };

    float acc[4][4][4];
#pragma unroll
    for (int mt = 0; mt < 4; mt++)
#pragma unroll
        for (int nt = 0; nt < 4; nt++)
#pragma unroll
            for (int r = 0; r < 4; r++) acc[mt][nt][r] = 0.f;

    const int a_row = lane & 15, a_seg = lane >> 4;
    const int b_g = lane >> 3,  b_r = lane & 7;

    issue(0, 0);
    issue(1, 1);
    for (int c = 0; c < NC; c++) {
        const int st = c % 3;
        if (c == NC - 1) {
            asm volatile("cp.async.wait_group 0;" ::: "memory");
        } else {
            asm volatile("cp.async.wait_group 1;" ::: "memory");
        }
        __syncthreads();

        const uint32_t a_b  = sb + st * STAGE_B;
        const uint32_t b_b  = a_b + TILE_B;

#pragma unroll
        for (int ks = 0; ks < 2; ks++) {
            const uint32_t acol = (uint32_t)(ks * 32 + a_seg * 16);
            const uint32_t bcol = (uint32_t)(ks * 32 + (b_g & 1) * 16);
            uint32_t ah[4][4], bh[2][4];
#pragma unroll
            for (int mt = 0; mt < 4; mt++) {
                uint32_t ro = (uint32_t)(wm * 64 + mt * 16 + a_row) * 64;
                ldsm4(ah[mt], a_b + swz64(ro + acol));
            }
#pragma unroll
            for (int np = 0; np < 2; np++) {
                uint32_t ro = (uint32_t)(wn * 32 + np * 16 + (b_g >> 1) * 8 + b_r) * 64;
                ldsm4(bh[np], b_b + swz64(ro + bcol));
            }
#pragma unroll
            for (int mt = 0; mt < 4; mt++)
#pragma unroll
                for (int nt = 0; nt < 4; nt++)
                    mma16816(acc[mt][nt], ah[mt], &bh[nt >> 1][(nt & 1) * 2]);
        }
        if (c + 2 < NC) issue(c + 2, (c + 2) % 3);
    }

    const int g  = lane >> 2;
    const int tc = lane & 3;
#pragma unroll
    for (int mt = 0; mt < 4; mt++) {
        float* r0 = C + (size_t)(m0 + wm * 64 + mt * 16 + g) * N + n0 + wn * 32;
        float* r1 = r0 + 8 * (size_t)N;
#pragma unroll
        for (int nt = 0; nt < 4; nt++) {
            *(float2*)(r0 + nt * 8 + tc * 2) = make_float2(acc[mt][nt][0], acc[mt][nt][1]);
            *(float2*)(r1 + nt * 8 + tc * 2) = make_float2(acc[mt][nt][2], acc[mt][nt][3]);
        }
    }
}

// ---------------- fused RoPE + fp16 store (q scaled, k, v) ------------------
__global__ void rope_split(const float* __restrict__ qkv,
                           const float* __restrict__ cosb, const float* __restrict__ sinb,
                           __half* __restrict__ qh,
                           __half* __restrict__ kh, __half* __restrict__ vh)
{
    const int QP = MROWS * NH * 32;
    const int KP = MROWS * NKV * 32;
    const int VP = MROWS * NKV * 32;
    int idx = blockIdx.x * blockDim.x + threadIdx.x;
    if (idx < QP) {
        int d    = idx & 31;
        int head = (idx >> 5) & (NH - 1);
        int bs   = idx >> 9;
        int s    = bs & (S_ - 1);
        size_t pi = (size_t)bs * NQKV + head * HD + d;
        size_t po = (size_t)bs * (NH * HD) + head * HD + d;
        float x0 = qkv[pi], x1 = qkv[pi + 32];
        float c0 = cosb[s * HD + d],      s0 = sinb[s * HD + d];
        float c1 = cosb[s * HD + d + 32], s1 = sinb[s * HD + d + 32];
        qh[po]      = __float2half_rn((x0 * c0 - x1 * s0) * QSCALE);
        qh[po + 32] = __float2half_rn((x1 * c1 + x0 * s1) * QSCALE);
    } else if (idx < QP + KP) {
        int r    = idx - QP;
        int d    = r & 31;
        int head = (r >> 5) & (NKV - 1);
        int bs   = r >> 7;
        int s    = bs & (S_ - 1);
        size_t pi = (size_t)bs * NQKV + 1024 + head * HD + d;
        size_t po = (size_t)bs * (NKV * HD) + head * HD + d;
        float x0 = qkv[pi], x1 = qkv[pi + 32];
        float c0 = cosb[s * HD + d],      s0 = sinb[s * HD + d];
        float c1 = cosb[s * HD + d + 32], s1 = sinb[s * HD + d + 32];
        kh[po]      = __float2half_rn(x0 * c0 - x1 * s0);
        kh[po + 32] = __float2half_rn(x1 * c1 + x0 * s1);
    } else if (idx < QP + KP + VP) {
        int r  = (idx - QP - KP) * 2;
        int bs = r >> 8, off = r & 255;
        size_t pi = (size_t)bs * NQKV + 1280 + off;
        ((__half2*)vh)[r >> 1] = __floats2half2_rn(qkv[pi], qkv[pi + 1]);
    }
}

// ---------------- fp16 flash attention (single-pass QK and PV) --------------
#define ATB 9216
#define ATT_SMEM (5 * ATB)

__global__ void __launch_bounds__(128, 4) attn_tc(
    const __half* __restrict__ Qh,
    const __half* __restrict__ Kh, const __half* __restrict__ Vh,
    __half* __restrict__ Oh)
{
    extern __shared__ char sm[];
    const uint32_t sb = smem_u32(sm);
    const uint32_t kbh[2] = {sb + 1 * ATB, sb + 3 * ATB};
    const uint32_t vbh[2] = {sb + 2 * ATB, sb + 4 * ATB};

    const int qt = (int)gridDim.x - 1 - (int)blockIdx.x;   // LPT: heavy first
    const int h = blockIdx.y, b = blockIdx.z;
    const int q0 = qt * 64;
    const int kv = h >> 2;
    const int tid = threadIdx.x, lane = tid & 31, w = tid >> 5;

    const int t0 = max(0, qt - 8);
    const int t1 = qt;

    auto load_kv = [&](int t, int st) {
        const size_t rb = ((size_t)(b * S_) + t * 64) * (NKV * HD) + kv * HD;
        const __half* src[2] = {Kh + rb, Vh + rb};
        const uint32_t dst[2] = {kbh[st], vbh[st]};
#pragma unroll
        for (int i = 0; i < 8; i++) {
            int c = tid + i * 128;
            int tb = c >> 9; int cc = c & 511;
            int rr = cc >> 3, sg = cc & 7;
            cpa16(dst[tb] + rr * 144 + sg * 16,
                  src[tb] + (size_t)rr * (NKV * HD) + sg * 8);
        }
        asm volatile("cp.async.commit_group;" ::: "memory");
    };

    {
        const __half* gqh = Qh + ((size_t)(b * S_) + q0) * (NH * HD) + h * HD;
#pragma unroll
        for (int i = 0; i < 4; i++) {
            int c = tid + i * 128;
            int rr = c >> 3, sg = c & 7;
            cpa16(sb + rr * 144 + sg * 16, gqh + (size_t)rr * (NH * HD) + sg * 8);
        }
    }
    load_kv(t0, 0);
    if (t0 < t1) {
        load_kv(t0 + 1, 1);
        asm volatile("cp.async.wait_group 1;" ::: "memory");   // group0 (Q+KV0) done
    } else {
        asm volatile("cp.async.wait_group 0;" ::: "memory");   // only one group
    }
    __syncthreads();

    uint32_t qf[4][4];
    {
        const uint32_t ro = (uint32_t)(w * 16 + (lane & 15)) * 144 + (lane >> 4) * 16;
#pragma unroll
        for (int ks = 0; ks < 4; ks++)
            ldsm4(qf[ks], sb + ro + ks * 32);
    }

    const int r0 = q0 + w * 16 + (lane >> 2);
    const int r1 = r0 + 8;
    float m0 = -1e30f, m1 = -1e30f, l0 = 0.f, l1 = 0.f;
    float oacc[8][4];
#pragma unroll
    for (int nt = 0; nt < 8; nt++)
#pragma unroll
        for (int c = 0; c < 4; c++) oacc[nt][c] = 0.f;

    for (int t = t0; t <= t1; t++) {
        const int st = (t - t0) & 1;
        const bool domask = (t == t1) || (t == t0 && qt >= 8);

        float sacc[8][4];
#pragma unroll
        for (int nt = 0; nt < 8; nt++)
#pragma unroll
            for (int c = 0; c < 4; c++) sacc[nt][c] = 0.f;

        const uint32_t kro = (uint32_t)(lane & 15) * 144 + (lane >> 4) * 16;
#pragma unroll
        for (int ks = 0; ks < 4; ks++) {
#pragma unroll
            for (int ntp = 0; ntp < 4; ntp++) {
                uint32_t kh[4];
                uint32_t ro = kro + (uint32_t)(ntp * 16) * 144 + ks * 32;
                ldsm4(kh, kbh[st] + ro);
                uint32_t bh0[2] = {kh[0], kh[2]}, bh1[2] = {kh[1], kh[3]};
                mma16816(sacc[2*ntp],   qf[ks], bh0);
                mma16816(sacc[2*ntp+1], qf[ks], bh1);
            }
        }

        float mx0 = -3e30f, mx1 = -3e30f;
        if (domask) {
#pragma unroll
            for (int nt = 0; nt < 8; nt++) {
                int kj = t * 64 + nt * 8 + 2 * (lane & 3);
                float v0 = ((kj   <= r0) && (r0 - kj   < WIN)) ? sacc[nt][0] : -3e30f;
                float v1 = ((kj+1 <= r0) && (r0 - kj-1 < WIN)) ? sacc[nt][1] : -3e30f;
                float v2 = ((kj   <= r1) && (r1 - kj   < WIN)) ? sacc[nt][2] : -3e30f;
                float v3 = ((kj+1 <= r1) && (r1 - kj-1 < WIN)) ? sacc[nt][3] : -3e30f;
                sacc[nt][0] = v0; sacc[nt][1] = v1; sacc[nt][2] = v2; sacc[nt][3] = v3;
                mx0 = fmaxf(mx0, fmaxf(v0, v1));
                mx1 = fmaxf(mx1, fmaxf(v2, v3));
            }
        } else {
#pragma unroll
            for (int nt = 0; nt < 8; nt++) {
                mx0 = fmaxf(mx0, fmaxf(sacc[nt][0], sacc[nt][1]));
                mx1 = fmaxf(mx1, fmaxf(sacc[nt][2], sacc[nt][3]));
            }
        }
        mx0 = fmaxf(mx0, __shfl_xor_sync(0xffffffffu, mx0, 1));
        mx0 = fmaxf(mx0, __shfl_xor_sync(0xffffffffu, mx0, 2));
        mx1 = fmaxf(mx1, __shfl_xor_sync(0xffffffffu, mx1, 1));
        mx1 = fmaxf(mx1, __shfl_xor_sync(0xffffffffu, mx1, 2));

        float mn0 = fmaxf(m0, mx0), mn1 = fmaxf(m1, mx1);
        float al0 = exp2f(m0 - mn0), al1 = exp2f(m1 - mn1);
        m0 = mn0; m1 = mn1;

        float rs0 = 0.f, rs1 = 0.f;
#pragma unroll
        for (int nt = 0; nt < 8; nt++) {
            float p0 = exp2f(sacc[nt][0] - mn0);
            float p1 = exp2f(sacc[nt][1] - mn0);
            float p2 = exp2f(sacc[nt][2] - mn1);
            float p3 = exp2f(sacc[nt][3] - mn1);
            sacc[nt][0] = p0; sacc[nt][1] = p1; sacc[nt][2] = p2; sacc[nt][3] = p3;
            rs0 += p0 + p1; rs1 += p2 + p3;
        }
        rs0 += __shfl_xor_sync(0xffffffffu, rs0, 1);
        rs0 += __shfl_xor_sync(0xffffffffu, rs0, 2);
        rs1 += __shfl_xor_sync(0xffffffffu, rs1, 1);
        rs1 += __shfl_xor_sync(0xffffffffu, rs1, 2);
        l0 = l0 * al0 + rs0; l1 = l1 * al1 + rs1;
#pragma unroll
        for (int nt = 0; nt < 8; nt++) {
            oacc[nt][0] *= al0; oacc[nt][1] *= al0;
            oacc[nt][2] *= al1; oacc[nt][3] *= al1;
        }

#pragma unroll
        for (int pk = 0; pk < 4; pk++) {
            uint32_t ah[4];
            ah[0] = packh2(sacc[2*pk][0],   sacc[2*pk][1]);
            ah[1] = packh2(sacc[2*pk][2],   sacc[2*pk][3]);
            ah[2] = packh2(sacc[2*pk+1][0], sacc[2*pk+1][1]);
            ah[3] = packh2(sacc[2*pk+1][2], sacc[2*pk+1][3]);
            const uint32_t vro = (uint32_t)(pk * 16 + (lane & 15)) * 144
                               + (uint32_t)(lane >> 4) * 16;
#pragma unroll
            for (int dp = 0; dp < 4; dp++) {
                uint32_t vh[4];
                ldsm4t(vh, vbh[st] + vro + dp * 32);
                mma16816(oacc[2*dp],   ah, &vh[0]);
                mma16816(oacc[2*dp+1], ah, &vh[2]);
            }
        }

        if (t < t1) {
            __syncthreads();
            if (t + 2 <= t1) {
                load_kv(t + 2, st);
                asm volatile("cp.async.wait_group 1;" ::: "memory");
            } else {
                asm volatile("cp.async.wait_group 0;" ::: "memory");
            }
            __syncthreads();
        }
    }

    const float inv0 = 1.f / l0, inv1 = 1.f / l1;
    const size_t rowA = (size_t)(b * S_) + r0;
    const size_t rowB = rowA + 8;
    const int colb = h * HD + 2 * (lane & 3);
#pragma unroll
    for (int nt = 0; nt < 8; nt++) {
        size_t offA = rowA * (NH * HD) + colb + nt * 8;
        size_t offB = rowB * (NH * HD) + colb + nt * 8;
        *(uint32_t*)(Oh + offA) = packh2(oacc[nt][0] * inv0, oacc[nt][1] * inv0);
        *(uint32_t*)(Oh + offB) = packh2(oacc[nt][2] * inv1, oacc[nt][3] * inv1);
    }
}

// ---------------- launch -----------------------------------------------------
extern "C" void kernel_launch(void* const* d_in, const int* in_sizes, int n_in,
                              void* d_out, int out_size)
{
    const float* hidden = (const float*)d_in[0];
    const float* cosb   = (const float*)d_in[1];
    const float* sinb   = (const float*)d_in[2];
    const float* Wq = (const float*)d_in[4];
    const float* Wk = (const float*)d_in[5];
    const float* Wv = (const float*)d_in[6];
    const float* Wo = (const float*)d_in[7];
    float* out = (float*)d_out;

    float* qkv;
    cudaGetSymbolAddress((void**)&qkv, g_qkv);
    __half *hh, *aoh, *wch, *woh, *qh, *kh, *vh;
    cudaGetSymbolAddress((void**)&hh,  g_hid_h);
    cudaGetSymbolAddress((void**)&aoh, g_ao_h);
    cudaGetSymbolAddress((void**)&wch, g_wc_h);
    cudaGetSymbolAddress((void**)&woh, g_wo_h);
    cudaGetSymbolAddress((void**)&qh,  g_qh);
    cudaGetSymbolAddress((void**)&kh,  g_kh);
    cudaGetSymbolAddress((void**)&vh,  g_vh);

    cudaFuncSetAttribute(gemm_tc, cudaFuncAttributeMaxDynamicSharedMemorySize, GEMM_SMEM);
    cudaFuncSetAttribute(attn_tc, cudaFuncAttributeMaxDynamicSharedMemorySize, ATT_SMEM);

    cvt_all<<<(1703936 + 255) / 256, 256>>>(hidden, Wq, Wk, Wv, Wo, hh, wch, woh);

    gemm_tc<<<dim3(NQKV / 128, MROWS / 128), 256, GEMM_SMEM>>>(hh, wch, qkv, NQKV, HM);

    int total = MROWS * NH * 32 + MROWS * NKV * 32 + MROWS * NKV * 32;
    rope_split<<<(total + 255) / 256, 256>>>(qkv, cosb, sinb, qh, kh, vh);

    attn_tc<<<dim3(S_ / 64, NH, B_), 128, ATT_SMEM>>>(qh, kh, vh, aoh);

    gemm_tc<<<dim3(HM / 128, MROWS / 128), 256, GEMM_SMEM>>>(aoh, woh, out, HM, HM);
}